// round 1
// baseline (speedup 1.0000x reference)
#include <cuda_runtime.h>
#include <cstdint>

static constexpr int NMAX = 100000;
static constexpr int D_ = 64;

// Scratch (static device globals — allowed; no runtime allocation)
__device__ __align__(256) float g_xn[NMAX * D_];
__device__ __align__(256) float g_agg[NMAX * D_];
__device__ __align__(256) float g_h[NMAX * D_];
__device__ __align__(256) float g_normx[NMAX];

__device__ __forceinline__ float warp_allreduce_sum(float v) {
#pragma unroll
    for (int o = 16; o; o >>= 1) v += __shfl_xor_sync(0xffffffffu, v, o);
    return v;
}

// ---------------------------------------------------------------------------
// Kernel 1: xn = l2norm(x); agg = xn; normx = ||x||.  One warp per node.
// ---------------------------------------------------------------------------
__global__ void k_prep(const float* __restrict__ x, int n) {
    int t = blockIdx.x * blockDim.x + threadIdx.x;
    int node = t >> 5, lane = t & 31;
    if (node >= n) return;
    float2 v = reinterpret_cast<const float2*>(x)[node * 32 + lane];
    float s = warp_allreduce_sum(v.x * v.x + v.y * v.y);
    float nrm = sqrtf(s);
    float inv = 1.0f / fmaxf(nrm, 1e-12f);
    float2 w = make_float2(v.x * inv, v.y * inv);
    reinterpret_cast<float2*>(g_xn)[node * 32 + lane] = w;
    reinterpret_cast<float2*>(g_agg)[node * 32 + lane] = w;
    if (lane == 0) g_normx[node] = nrm;
}

// ---------------------------------------------------------------------------
// Kernel 2: agg[dst] += xn[src].  16 threads/edge, vector (128-bit) reductions.
// xn table (25.6MB) is L2-resident -> L2/atomic-throughput bound.
// ---------------------------------------------------------------------------
__global__ void k_scatter(const int* __restrict__ src, const int* __restrict__ dst, int E) {
    int t = blockIdx.x * blockDim.x + threadIdx.x;
    int e = t >> 4, i = t & 15;
    if (e >= E) return;
    int s = src[e], d = dst[e];
    float4 v = reinterpret_cast<const float4*>(g_xn)[s * 16 + i];
    unsigned long long p =
        __cvta_generic_to_global(&reinterpret_cast<float4*>(g_agg)[d * 16 + i]);
    asm volatile("red.global.add.v4.f32 [%0], {%1,%2,%3,%4};"
                 :: "l"(p), "f"(v.x), "f"(v.y), "f"(v.z), "f"(v.w)
                 : "memory");
}

// ---------------------------------------------------------------------------
// Kernel 3: per-node epilogue + dual GEMM + final l2norm (+relu / next-layer
// prep when FIRST).  32 nodes per 256-thread block.
//   msg = l2norm(agg) * normx * scale
//   out = msg @ Wl^T + bl + x @ Wr^T ; out = l2norm(out)
// W tiles in smem with row stride 68 (conflict-free LDS.128).
// ---------------------------------------------------------------------------
template <bool FIRST>
__global__ void k_update(const float* __restrict__ xin_param,
                         const float* __restrict__ Wl, const float* __restrict__ bl,
                         const float* __restrict__ Wr, const float* __restrict__ scale_p,
                         float* __restrict__ out, int n) {
    extern __shared__ float sm[];
    float* sWl  = sm;                  // 64 * 68
    float* sWr  = sm + 64 * 68;        // 64 * 68
    float* sMsg = sWr + 64 * 68;       // 32 * 64
    float* sX   = sMsg + 32 * 64;      // 32 * 64
    const int tid = threadIdx.x;
    const int base = blockIdx.x * 32;

    const float* xin = FIRST ? xin_param : g_h;

    // Load both weight matrices into padded smem
    for (int i = tid; i < 4096; i += 256) {
        int j = i >> 6, k = i & 63;
        sWl[j * 68 + k] = Wl[i];
        sWr[j * 68 + k] = Wr[i];
    }

    // Stage 1: msg + x rows into smem. 8 threads per node.
    {
        int nloc = tid >> 3, c = tid & 7;
        int node = base + nloc;
        bool valid = node < n;
        int rnode = valid ? node : (n - 1);
        const float4* ap = reinterpret_cast<const float4*>(g_agg + rnode * 64);
        float4 a0 = ap[c * 2], a1 = ap[c * 2 + 1];
        float s = a0.x*a0.x + a0.y*a0.y + a0.z*a0.z + a0.w*a0.w
                + a1.x*a1.x + a1.y*a1.y + a1.z*a1.z + a1.w*a1.w;
#pragma unroll
        for (int o = 4; o; o >>= 1) s += __shfl_xor_sync(0xffffffffu, s, o);
        float f = g_normx[rnode] * scale_p[0] / fmaxf(sqrtf(s), 1e-12f);
        float4* mp = reinterpret_cast<float4*>(sMsg + nloc * 64);
        mp[c * 2]     = make_float4(a0.x*f, a0.y*f, a0.z*f, a0.w*f);
        mp[c * 2 + 1] = make_float4(a1.x*f, a1.y*f, a1.z*f, a1.w*f);
        const float4* xp = reinterpret_cast<const float4*>(xin + rnode * 64);
        float4* sxp = reinterpret_cast<float4*>(sX + nloc * 64);
        sxp[c * 2]     = xp[c * 2];
        sxp[c * 2 + 1] = xp[c * 2 + 1];
    }
    __syncthreads();

    // Stage 2: GEMM. Warp w handles nodes [w*4, w*4+4); lane = output j, j+32.
    const int w = tid >> 5, lane = tid & 31;
    const int nb = w * 4;
    float acc0[4] = {0, 0, 0, 0}, acc1[4] = {0, 0, 0, 0};
    const float4* wl0p = reinterpret_cast<const float4*>(sWl + lane * 68);
    const float4* wl1p = reinterpret_cast<const float4*>(sWl + (lane + 32) * 68);
    const float4* wr0p = reinterpret_cast<const float4*>(sWr + lane * 68);
    const float4* wr1p = reinterpret_cast<const float4*>(sWr + (lane + 32) * 68);
#pragma unroll 4
    for (int k4 = 0; k4 < 16; k4++) {
        float4 wl0 = wl0p[k4], wl1 = wl1p[k4];
        float4 wr0 = wr0p[k4], wr1 = wr1p[k4];
#pragma unroll
        for (int m = 0; m < 4; m++) {
            float4 mg = reinterpret_cast<const float4*>(sMsg + (nb + m) * 64)[k4];
            float4 xv = reinterpret_cast<const float4*>(sX + (nb + m) * 64)[k4];
            acc0[m] += wl0.x*mg.x + wl0.y*mg.y + wl0.z*mg.z + wl0.w*mg.w;
            acc0[m] += wr0.x*xv.x + wr0.y*xv.y + wr0.z*xv.z + wr0.w*xv.w;
            acc1[m] += wl1.x*mg.x + wl1.y*mg.y + wl1.z*mg.z + wl1.w*mg.w;
            acc1[m] += wr1.x*xv.x + wr1.y*xv.y + wr1.z*xv.z + wr1.w*xv.w;
        }
    }

    float b0 = bl[lane], b1 = bl[lane + 32];
#pragma unroll
    for (int m = 0; m < 4; m++) {
        int node = base + nb + m;          // warp-uniform
        if (node < n) {
            float o0 = acc0[m] + b0, o1 = acc1[m] + b1;
            float s = warp_allreduce_sum(o0 * o0 + o1 * o1);
            float inv = 1.0f / fmaxf(sqrtf(s), 1e-12f);
            o0 *= inv; o1 *= inv;
            if (FIRST) {
                // relu, then pre-compute next layer's xn / agg / normx
                o0 = fmaxf(o0, 0.0f); o1 = fmaxf(o1, 0.0f);
                float s2 = warp_allreduce_sum(o0 * o0 + o1 * o1);
                float nrm2 = sqrtf(s2);
                float inv2 = 1.0f / fmaxf(nrm2, 1e-12f);
                float xn0 = o0 * inv2, xn1 = o1 * inv2;
                g_h[node * 64 + lane]       = o0;
                g_h[node * 64 + lane + 32]  = o1;
                g_xn[node * 64 + lane]      = xn0;
                g_xn[node * 64 + lane + 32] = xn1;
                g_agg[node * 64 + lane]      = xn0;
                g_agg[node * 64 + lane + 32] = xn1;
                if (lane == 0) g_normx[node] = nrm2;
            } else {
                out[node * 64 + lane]      = o0;
                out[node * 64 + lane + 32] = o1;
            }
        }
    }
}

// ---------------------------------------------------------------------------
extern "C" void kernel_launch(void* const* d_in, const int* in_sizes, int n_in,
                              void* d_out, int out_size) {
    const float* x   = (const float*)d_in[0];
    const float* Wl0 = (const float*)d_in[1];
    const float* bl0 = (const float*)d_in[2];
    const float* Wr0 = (const float*)d_in[3];
    const float* sc0 = (const float*)d_in[4];
    const float* Wl1 = (const float*)d_in[5];
    const float* bl1 = (const float*)d_in[6];
    const float* Wr1 = (const float*)d_in[7];
    const float* sc1 = (const float*)d_in[8];
    const int*   ei  = (const int*)d_in[9];

    int n = in_sizes[0] / 64;
    int E = in_sizes[9] / 2;
    const int* src = ei;
    const int* dst = ei + E;
    float* out = (float*)d_out;

    const int smem = (64 * 68 * 2 + 32 * 64 * 2) * (int)sizeof(float);  // 51200 B
    cudaFuncSetAttribute(k_update<true>,  cudaFuncAttributeMaxDynamicSharedMemorySize, smem);
    cudaFuncSetAttribute(k_update<false>, cudaFuncAttributeMaxDynamicSharedMemorySize, smem);

    int gp = (n * 32 + 255) / 256;
    int gs = (E * 16 + 255) / 256;
    int gu = (n + 31) / 32;

    // Layer 0
    k_prep<<<gp, 256>>>(x, n);
    k_scatter<<<gs, 256>>>(src, dst, E);
    k_update<true><<<gu, 256, smem>>>(x, Wl0, bl0, Wr0, sc0, nullptr, n);
    // Layer 1 (input prep fused into k_update<true>)
    k_scatter<<<gs, 256>>>(src, dst, E);
    k_update<false><<<gu, 256, smem>>>(x, Wl1, bl1, Wr1, sc1, out, n);
}

// round 2
// speedup vs baseline: 1.0989x; 1.0989x over previous
#include <cuda_runtime.h>
#include <cstdint>

static constexpr int NMAX = 100000;
static constexpr int D_ = 64;

// Scratch (static device globals — no runtime allocation)
__device__ __align__(256) float g_xn[NMAX * D_];
__device__ __align__(256) float g_agg[NMAX * D_];
__device__ __align__(256) float g_h[NMAX * D_];
__device__ __align__(256) float g_normx[NMAX];

__device__ __forceinline__ float warp_allreduce_sum(float v) {
#pragma unroll
    for (int o = 16; o; o >>= 1) v += __shfl_xor_sync(0xffffffffu, v, o);
    return v;
}

__device__ __forceinline__ void red_add_v4(float4* p, float4 v) {
    unsigned long long a = __cvta_generic_to_global(p);
    asm volatile("red.global.add.v4.f32 [%0], {%1,%2,%3,%4};"
                 :: "l"(a), "f"(v.x), "f"(v.y), "f"(v.z), "f"(v.w)
                 : "memory");
}

// ---------------------------------------------------------------------------
// Kernel 1: xn = l2norm(x); agg = xn; normx = ||x||.  One warp per node.
// ---------------------------------------------------------------------------
__global__ void k_prep(const float* __restrict__ x, int n) {
    int t = blockIdx.x * blockDim.x + threadIdx.x;
    int node = t >> 5, lane = t & 31;
    if (node >= n) return;
    float2 v = reinterpret_cast<const float2*>(x)[node * 32 + lane];
    float s = warp_allreduce_sum(v.x * v.x + v.y * v.y);
    float nrm = sqrtf(s);
    float inv = 1.0f / fmaxf(nrm, 1e-12f);
    float2 w = make_float2(v.x * inv, v.y * inv);
    reinterpret_cast<float2*>(g_xn)[node * 32 + lane] = w;
    reinterpret_cast<float2*>(g_agg)[node * 32 + lane] = w;
    if (lane == 0) g_normx[node] = nrm;
}

// ---------------------------------------------------------------------------
// Kernel 2: agg[dst] += xn[src].  4 threads/edge, 4x float4 per thread.
// MLP=4 gathers, then 4 vector reductions. Index loads: 8/edge (was 32).
// ---------------------------------------------------------------------------
__global__ void k_scatter(const int* __restrict__ src, const int* __restrict__ dst, int E) {
    int t = blockIdx.x * blockDim.x + threadIdx.x;
    int e = t >> 2, q = t & 3;
    if (e >= E) return;
    int s = src[e], d = dst[e];
    const float4* sp = reinterpret_cast<const float4*>(g_xn) + s * 16 + q;
    float4* dp = reinterpret_cast<float4*>(g_agg) + d * 16 + q;
    float4 v0 = sp[0];
    float4 v1 = sp[4];
    float4 v2 = sp[8];
    float4 v3 = sp[12];
    red_add_v4(dp + 0,  v0);
    red_add_v4(dp + 4,  v1);
    red_add_v4(dp + 8,  v2);
    red_add_v4(dp + 12, v3);
}

// ---------------------------------------------------------------------------
// Kernel 3: per-node epilogue + dual GEMM + final l2norm (+relu / next-layer
// prep when FIRST).  64 nodes per 256-thread block, 8 nodes per warp.
//   msg = l2norm(agg) * normx * scale
//   out = msg @ Wl^T + bl + x @ Wr^T ; out = l2norm(out)
// ---------------------------------------------------------------------------
template <bool FIRST>
__global__ void k_update(const float* __restrict__ xin_param,
                         const float* __restrict__ Wl, const float* __restrict__ bl,
                         const float* __restrict__ Wr, const float* __restrict__ scale_p,
                         float* __restrict__ out, int n) {
    extern __shared__ float sm[];
    float* sWl  = sm;                  // 64 * 68
    float* sWr  = sm + 64 * 68;        // 64 * 68
    float* sMsg = sWr + 64 * 68;       // 64 * 64
    float* sX   = sMsg + 64 * 64;      // 64 * 64
    const int tid = threadIdx.x;
    const int base = blockIdx.x * 64;

    const float* xin = FIRST ? xin_param : g_h;

    // Load both weight matrices into padded smem
    for (int i = tid; i < 4096; i += 256) {
        int j = i >> 6, k = i & 63;
        sWl[j * 68 + k] = Wl[i];
        sWr[j * 68 + k] = Wr[i];
    }

    // Stage 1: msg + x rows into smem. 4 threads per node, 4 float4 each.
    {
        int nloc = tid >> 2, c = tid & 3;
        int node = base + nloc;
        int rnode = (node < n) ? node : (n - 1);
        const float4* ap = reinterpret_cast<const float4*>(g_agg + rnode * 64) + c;
        float4 a0 = ap[0], a1 = ap[4], a2 = ap[8], a3 = ap[12];
        float s = a0.x*a0.x + a0.y*a0.y + a0.z*a0.z + a0.w*a0.w
                + a1.x*a1.x + a1.y*a1.y + a1.z*a1.z + a1.w*a1.w
                + a2.x*a2.x + a2.y*a2.y + a2.z*a2.z + a2.w*a2.w
                + a3.x*a3.x + a3.y*a3.y + a3.z*a3.z + a3.w*a3.w;
        s += __shfl_xor_sync(0xffffffffu, s, 1);
        s += __shfl_xor_sync(0xffffffffu, s, 2);
        float f = g_normx[rnode] * scale_p[0] / fmaxf(sqrtf(s), 1e-12f);
        float4* mp = reinterpret_cast<float4*>(sMsg + nloc * 64) + c;
        mp[0]  = make_float4(a0.x*f, a0.y*f, a0.z*f, a0.w*f);
        mp[4]  = make_float4(a1.x*f, a1.y*f, a1.z*f, a1.w*f);
        mp[8]  = make_float4(a2.x*f, a2.y*f, a2.z*f, a2.w*f);
        mp[12] = make_float4(a3.x*f, a3.y*f, a3.z*f, a3.w*f);
        const float4* xp = reinterpret_cast<const float4*>(xin + rnode * 64) + c;
        float4* sxp = reinterpret_cast<float4*>(sX + nloc * 64) + c;
        sxp[0]  = xp[0];
        sxp[4]  = xp[4];
        sxp[8]  = xp[8];
        sxp[12] = xp[12];
    }
    __syncthreads();

    // Stage 2: GEMM. Warp w handles nodes [w*8, w*8+8); lane = output j, j+32.
    const int w = tid >> 5, lane = tid & 31;
    const int nb = w * 8;
    float acc0[8] = {0,0,0,0,0,0,0,0}, acc1[8] = {0,0,0,0,0,0,0,0};
    const float4* wl0p = reinterpret_cast<const float4*>(sWl + lane * 68);
    const float4* wl1p = reinterpret_cast<const float4*>(sWl + (lane + 32) * 68);
    const float4* wr0p = reinterpret_cast<const float4*>(sWr + lane * 68);
    const float4* wr1p = reinterpret_cast<const float4*>(sWr + (lane + 32) * 68);
#pragma unroll 2
    for (int k4 = 0; k4 < 16; k4++) {
        float4 wl0 = wl0p[k4], wl1 = wl1p[k4];
        float4 wr0 = wr0p[k4], wr1 = wr1p[k4];
#pragma unroll
        for (int m = 0; m < 8; m++) {
            float4 mg = reinterpret_cast<const float4*>(sMsg + (nb + m) * 64)[k4];
            float4 xv = reinterpret_cast<const float4*>(sX + (nb + m) * 64)[k4];
            acc0[m] += wl0.x*mg.x + wl0.y*mg.y + wl0.z*mg.z + wl0.w*mg.w;
            acc0[m] += wr0.x*xv.x + wr0.y*xv.y + wr0.z*xv.z + wr0.w*xv.w;
            acc1[m] += wl1.x*mg.x + wl1.y*mg.y + wl1.z*mg.z + wl1.w*mg.w;
            acc1[m] += wr1.x*xv.x + wr1.y*xv.y + wr1.z*xv.z + wr1.w*xv.w;
        }
    }

    float b0 = bl[lane], b1 = bl[lane + 32];
#pragma unroll
    for (int m = 0; m < 8; m++) {
        int node = base + nb + m;          // warp-uniform
        if (node < n) {
            float o0 = acc0[m] + b0, o1 = acc1[m] + b1;
            float s = warp_allreduce_sum(o0 * o0 + o1 * o1);
            float inv = 1.0f / fmaxf(sqrtf(s), 1e-12f);
            o0 *= inv; o1 *= inv;
            if (FIRST) {
                // relu, then pre-compute next layer's xn / agg / normx
                o0 = fmaxf(o0, 0.0f); o1 = fmaxf(o1, 0.0f);
                float s2 = warp_allreduce_sum(o0 * o0 + o1 * o1);
                float nrm2 = sqrtf(s2);
                float inv2 = 1.0f / fmaxf(nrm2, 1e-12f);
                float xn0 = o0 * inv2, xn1 = o1 * inv2;
                g_h[node * 64 + lane]       = o0;
                g_h[node * 64 + lane + 32]  = o1;
                g_xn[node * 64 + lane]      = xn0;
                g_xn[node * 64 + lane + 32] = xn1;
                g_agg[node * 64 + lane]      = xn0;
                g_agg[node * 64 + lane + 32] = xn1;
                if (lane == 0) g_normx[node] = nrm2;
            } else {
                out[node * 64 + lane]      = o0;
                out[node * 64 + lane + 32] = o1;
            }
        }
    }
}

// ---------------------------------------------------------------------------
extern "C" void kernel_launch(void* const* d_in, const int* in_sizes, int n_in,
                              void* d_out, int out_size) {
    const float* x   = (const float*)d_in[0];
    const float* Wl0 = (const float*)d_in[1];
    const float* bl0 = (const float*)d_in[2];
    const float* Wr0 = (const float*)d_in[3];
    const float* sc0 = (const float*)d_in[4];
    const float* Wl1 = (const float*)d_in[5];
    const float* bl1 = (const float*)d_in[6];
    const float* Wr1 = (const float*)d_in[7];
    const float* sc1 = (const float*)d_in[8];
    const int*   ei  = (const int*)d_in[9];

    int n = in_sizes[0] / 64;
    int E = in_sizes[9] / 2;
    const int* src = ei;
    const int* dst = ei + E;
    float* out = (float*)d_out;

    const int smem = (64 * 68 * 2 + 64 * 64 * 2) * (int)sizeof(float);  // 67584 B
    cudaFuncSetAttribute(k_update<true>,  cudaFuncAttributeMaxDynamicSharedMemorySize, smem);
    cudaFuncSetAttribute(k_update<false>, cudaFuncAttributeMaxDynamicSharedMemorySize, smem);

    int gp = (n * 32 + 255) / 256;
    int gs = (E * 4 + 255) / 256;
    int gu = (n + 63) / 64;

    // Layer 0
    k_prep<<<gp, 256>>>(x, n);
    k_scatter<<<gs, 256>>>(src, dst, E);
    k_update<true><<<gu, 256, smem>>>(x, Wl0, bl0, Wr0, sc0, nullptr, n);
    // Layer 1 (input prep fused into k_update<true>)
    k_scatter<<<gs, 256>>>(src, dst, E);
    k_update<false><<<gu, 256, smem>>>(x, Wl1, bl1, Wr1, sc1, out, n);
}

// round 3
// speedup vs baseline: 1.2696x; 1.1553x over previous
#include <cuda_runtime.h>
#include <cstdint>

static constexpr int NMAX = 100000;
static constexpr int EMAX = 1300000;
static constexpr int D_ = 64;

// Scratch (static device globals — no runtime allocation)
__device__ __align__(256) float g_xn[NMAX * D_];    // normalized input of current layer
__device__ __align__(256) float g_msg[NMAX * D_];   // scaled message (gather output)
__device__ __align__(256) float g_h[NMAX * D_];     // layer-0 output (relu'd)
__device__ __align__(256) float g_normx[NMAX];
__device__ int g_deg[NMAX];
__device__ int g_off[NMAX];
__device__ int g_cur[NMAX];
__device__ int g_csr[EMAX];
__device__ int g_total;

__device__ __forceinline__ float warp_allreduce_sum(float v) {
#pragma unroll
    for (int o = 16; o; o >>= 1) v += __shfl_xor_sync(0xffffffffu, v, o);
    return v;
}

// ---------------------------------------------------------------------------
// CSR build
// ---------------------------------------------------------------------------
__global__ void k_zero(int n) {
    int t = blockIdx.x * blockDim.x + threadIdx.x;
    if (t < n) g_deg[t] = 0;
    if (t == 0) g_total = 0;
}

__global__ void k_hist(const int* __restrict__ dst, int E) {
    int e = blockIdx.x * blockDim.x + threadIdx.x;
    if (e < E) atomicAdd(&g_deg[dst[e]], 1);
}

// Warp-aggregated offset reservation (order nondeterministic; only list
// placement varies, per-node sums are over the same multiset).
__global__ void k_resv(int n) {
    int v = blockIdx.x * blockDim.x + threadIdx.x;
    int lane = threadIdx.x & 31;
    int d = (v < n) ? g_deg[v] : 0;
    int incl = d;
#pragma unroll
    for (int o = 1; o < 32; o <<= 1) {
        int t = __shfl_up_sync(0xffffffffu, incl, o);
        if (lane >= o) incl += t;
    }
    int wsum = __shfl_sync(0xffffffffu, incl, 31);
    int base = 0;
    if (lane == 31) base = atomicAdd(&g_total, wsum);
    base = __shfl_sync(0xffffffffu, base, 31);
    if (v < n) {
        int o = base + incl - d;
        g_off[v] = o;
        g_cur[v] = o;
    }
}

__global__ void k_fill(const int* __restrict__ src, const int* __restrict__ dst, int E) {
    int e = blockIdx.x * blockDim.x + threadIdx.x;
    if (e < E) {
        int p = atomicAdd(&g_cur[dst[e]], 1);
        g_csr[p] = src[e];
    }
}

// ---------------------------------------------------------------------------
// k_prep: xn = l2norm(x); normx = ||x||.  One warp per node.
// ---------------------------------------------------------------------------
__global__ void k_prep(const float* __restrict__ x, int n) {
    int t = blockIdx.x * blockDim.x + threadIdx.x;
    int node = t >> 5, lane = t & 31;
    if (node >= n) return;
    float2 v = reinterpret_cast<const float2*>(x)[node * 32 + lane];
    float s = warp_allreduce_sum(v.x * v.x + v.y * v.y);
    float nrm = sqrtf(s);
    float inv = 1.0f / fmaxf(nrm, 1e-12f);
    reinterpret_cast<float2*>(g_xn)[node * 32 + lane] = make_float2(v.x * inv, v.y * inv);
    if (lane == 0) g_normx[node] = nrm;
}

// ---------------------------------------------------------------------------
// k_gather: one warp per node. agg = xn[v] + sum_{s in CSR[v]} xn[s];
// msg = l2norm(agg) * normx[v] * scale  -> g_msg.   No atomics.
// ---------------------------------------------------------------------------
__global__ void k_gather(const float* __restrict__ scale_p, int n) {
    int t = blockIdx.x * blockDim.x + threadIdx.x;
    int node = t >> 5, lane = t & 31;
    if (node >= n) return;
    const float2* xn2 = reinterpret_cast<const float2*>(g_xn);
    float2 acc = xn2[node * 32 + lane];
    int off = g_off[node], deg = g_deg[node];
    int j = 0;
    for (; j + 4 <= deg; j += 4) {                 // MLP=4 independent row loads
        int s0 = g_csr[off + j], s1 = g_csr[off + j + 1];
        int s2 = g_csr[off + j + 2], s3 = g_csr[off + j + 3];
        float2 v0 = xn2[s0 * 32 + lane];
        float2 v1 = xn2[s1 * 32 + lane];
        float2 v2 = xn2[s2 * 32 + lane];
        float2 v3 = xn2[s3 * 32 + lane];
        acc.x += v0.x + v1.x + v2.x + v3.x;
        acc.y += v0.y + v1.y + v2.y + v3.y;
    }
    for (; j < deg; j++) {
        int s = g_csr[off + j];
        float2 v = xn2[s * 32 + lane];
        acc.x += v.x; acc.y += v.y;
    }
    float ss = warp_allreduce_sum(acc.x * acc.x + acc.y * acc.y);
    float f = g_normx[node] * scale_p[0] / fmaxf(sqrtf(ss), 1e-12f);
    reinterpret_cast<float2*>(g_msg)[node * 32 + lane] =
        make_float2(acc.x * f, acc.y * f);
}

// ---------------------------------------------------------------------------
// k_update: dual GEMM + final l2norm (+relu / next-layer prep when FIRST).
// 64 nodes per 256-thread block, 8 nodes per warp.
//   out = msg @ Wl^T + bl + x @ Wr^T ; out = l2norm(out)
// ---------------------------------------------------------------------------
template <bool FIRST>
__global__ void k_update(const float* __restrict__ xin_param,
                         const float* __restrict__ Wl, const float* __restrict__ bl,
                         const float* __restrict__ Wr,
                         float* __restrict__ out, int n) {
    extern __shared__ float sm[];
    float* sWl  = sm;                  // 64 * 68
    float* sWr  = sm + 64 * 68;        // 64 * 68
    float* sMsg = sWr + 64 * 68;       // 64 * 64
    float* sX   = sMsg + 64 * 64;      // 64 * 64
    const int tid = threadIdx.x;
    const int base = blockIdx.x * 64;

    const float* xin = FIRST ? xin_param : g_h;

    for (int i = tid; i < 4096; i += 256) {
        int j = i >> 6, k = i & 63;
        sWl[j * 68 + k] = Wl[i];
        sWr[j * 68 + k] = Wr[i];
    }

    // Stage 1: plain copy of msg + x rows to smem. 4 threads per node.
    {
        int nloc = tid >> 2, c = tid & 3;
        int node = base + nloc;
        int rnode = (node < n) ? node : (n - 1);
        const float4* mg = reinterpret_cast<const float4*>(g_msg + rnode * 64) + c;
        float4* mp = reinterpret_cast<float4*>(sMsg + nloc * 64) + c;
        mp[0]  = mg[0];  mp[4]  = mg[4];  mp[8]  = mg[8];  mp[12] = mg[12];
        const float4* xp = reinterpret_cast<const float4*>(xin + rnode * 64) + c;
        float4* sxp = reinterpret_cast<float4*>(sX + nloc * 64) + c;
        sxp[0]  = xp[0]; sxp[4]  = xp[4]; sxp[8]  = xp[8]; sxp[12] = xp[12];
    }
    __syncthreads();

    // Stage 2: GEMM. Warp w handles nodes [w*8, w*8+8); lane = outputs j, j+32.
    const int w = tid >> 5, lane = tid & 31;
    const int nb = w * 8;
    float acc0[8] = {0,0,0,0,0,0,0,0}, acc1[8] = {0,0,0,0,0,0,0,0};
    const float4* wl0p = reinterpret_cast<const float4*>(sWl + lane * 68);
    const float4* wl1p = reinterpret_cast<const float4*>(sWl + (lane + 32) * 68);
    const float4* wr0p = reinterpret_cast<const float4*>(sWr + lane * 68);
    const float4* wr1p = reinterpret_cast<const float4*>(sWr + (lane + 32) * 68);
#pragma unroll 2
    for (int k4 = 0; k4 < 16; k4++) {
        float4 wl0 = wl0p[k4], wl1 = wl1p[k4];
        float4 wr0 = wr0p[k4], wr1 = wr1p[k4];
#pragma unroll
        for (int m = 0; m < 8; m++) {
            float4 mg = reinterpret_cast<const float4*>(sMsg + (nb + m) * 64)[k4];
            float4 xv = reinterpret_cast<const float4*>(sX + (nb + m) * 64)[k4];
            acc0[m] += wl0.x*mg.x + wl0.y*mg.y + wl0.z*mg.z + wl0.w*mg.w;
            acc0[m] += wr0.x*xv.x + wr0.y*xv.y + wr0.z*xv.z + wr0.w*xv.w;
            acc1[m] += wl1.x*mg.x + wl1.y*mg.y + wl1.z*mg.z + wl1.w*mg.w;
            acc1[m] += wr1.x*xv.x + wr1.y*xv.y + wr1.z*xv.z + wr1.w*xv.w;
        }
    }

    float b0 = bl[lane], b1 = bl[lane + 32];
#pragma unroll
    for (int m = 0; m < 8; m++) {
        int node = base + nb + m;          // warp-uniform
        if (node < n) {
            float o0 = acc0[m] + b0, o1 = acc1[m] + b1;
            float s = warp_allreduce_sum(o0 * o0 + o1 * o1);
            float inv = 1.0f / fmaxf(sqrtf(s), 1e-12f);
            o0 *= inv; o1 *= inv;
            if (FIRST) {
                // relu, then pre-compute next layer's xn / normx
                o0 = fmaxf(o0, 0.0f); o1 = fmaxf(o1, 0.0f);
                float s2 = warp_allreduce_sum(o0 * o0 + o1 * o1);
                float nrm2 = sqrtf(s2);
                float inv2 = 1.0f / fmaxf(nrm2, 1e-12f);
                g_h[node * 64 + lane]       = o0;
                g_h[node * 64 + lane + 32]  = o1;
                g_xn[node * 64 + lane]      = o0 * inv2;
                g_xn[node * 64 + lane + 32] = o1 * inv2;
                if (lane == 0) g_normx[node] = nrm2;
            } else {
                out[node * 64 + lane]      = o0;
                out[node * 64 + lane + 32] = o1;
            }
        }
    }
}

// ---------------------------------------------------------------------------
extern "C" void kernel_launch(void* const* d_in, const int* in_sizes, int n_in,
                              void* d_out, int out_size) {
    const float* x   = (const float*)d_in[0];
    const float* Wl0 = (const float*)d_in[1];
    const float* bl0 = (const float*)d_in[2];
    const float* Wr0 = (const float*)d_in[3];
    const float* sc0 = (const float*)d_in[4];
    const float* Wl1 = (const float*)d_in[5];
    const float* bl1 = (const float*)d_in[6];
    const float* Wr1 = (const float*)d_in[7];
    const float* sc1 = (const float*)d_in[8];
    const int*   ei  = (const int*)d_in[9];

    int n = in_sizes[0] / 64;
    int E = in_sizes[9] / 2;
    const int* src = ei;
    const int* dst = ei + E;
    float* out = (float*)d_out;

    const int smem = (64 * 68 * 2 + 64 * 64 * 2) * (int)sizeof(float);  // 67584 B
    cudaFuncSetAttribute(k_update<true>,  cudaFuncAttributeMaxDynamicSharedMemorySize, smem);
    cudaFuncSetAttribute(k_update<false>, cudaFuncAttributeMaxDynamicSharedMemorySize, smem);

    int gn  = (n + 255) / 256;            // per-node, 1 thread
    int ge  = (E + 255) / 256;            // per-edge, 1 thread
    int gw  = (n * 32 + 255) / 256;       // per-node, 1 warp
    int gu  = (n + 63) / 64;

    // CSR build (used by both layers)
    k_zero<<<gn, 256>>>(n);
    k_prep<<<gw, 256>>>(x, n);
    k_hist<<<ge, 256>>>(dst, E);
    k_resv<<<gn, 256>>>(n);
    k_fill<<<ge, 256>>>(src, dst, E);

    // Layer 0
    k_gather<<<gw, 256>>>(sc0, n);
    k_update<true><<<gu, 256, smem>>>(x, Wl0, bl0, Wr0, nullptr, n);
    // Layer 1 (input prep fused into k_update<true>)
    k_gather<<<gw, 256>>>(sc1, n);
    k_update<false><<<gu, 256, smem>>>(x, Wl1, bl1, Wr1, out, n);
}